// round 6
// baseline (speedup 1.0000x reference)
#include <cuda_runtime.h>
#include <math.h>
#include <stdint.h>

#define NPIX   65536      // 256*256
#define PCOUNT 1024       // 4 * 16 * 16 patches
#define NB     512        // 8^3 bins
#define SINK_EPS 1e-6f

#define BM 64
#define BN 64
#define BK 16
#define KHALF 256                 // K per warp-group
#define NKC (KHALF / BK)          // 16 chunks per group

// dynamic smem layout (floats):
//   As: [2 groups][2 buf][16][64]   = 4096 floats (16KB)   at offset 0
//   Bs: [2 groups][2 buf][16][128]  = 8192 floats (32KB)   at offset 4096 (B pre-duplicated pairs)
//   epilogue: stage = offset 0 (32*128 = 4096 floats), red = offset 4096 (64*16)
#define SMEM_FLOATS 12288

// ---------------- scratch (static device globals; no allocation) ----------------
__device__ float    g_oklab[2][4 * 3 * NPIX];   // [img][b][c][h][w]
__device__ unsigned g_mm[12];                   // [0:6) min enc (img,c), [6:12) max enc
__device__ float    g_hist[2][PCOUNT * NB];     // normalized (counts/256)
__device__ float    g_u[PCOUNT * NB];
__device__ float    g_v[PCOUNT * NB];
__device__ float    g_K[NB * NB];
__device__ float    g_KC[NB * NB];              // K * cost
__device__ float    g_emd[PCOUNT];

typedef unsigned long long ull;

// packed fp32x2 FMA: d = a*b + d (two independent lanes)
__device__ __forceinline__ void ffma2(ull& d, ull a, ull b) {
    asm("fma.rn.f32x2 %0, %1, %2, %0;" : "+l"(d) : "l"(a), "l"(b));
}
__device__ __forceinline__ float lo_f(ull p) { return __uint_as_float((unsigned)p); }
__device__ __forceinline__ float hi_f(ull p) { return __uint_as_float((unsigned)(p >> 32)); }

#define GBAR(gid) asm volatile("bar.sync %0, 128;" :: "r"((gid) + 1) : "memory")

// ---------------- helpers ----------------
__device__ __forceinline__ unsigned fenc(float f) {
    unsigned u = __float_as_uint(f);
    return (u & 0x80000000u) ? ~u : (u | 0x80000000u);
}
__device__ __forceinline__ float fdec(unsigned u) {
    return __uint_as_float((u & 0x80000000u) ? (u ^ 0x80000000u) : ~u);
}
__device__ __forceinline__ float srgb_lin(float x) {
    x = fminf(fmaxf(x, 0.0f), 1.0f);
    return (x <= 0.04045f) ? x * (1.0f / 12.92f)
                           : powf((x + 0.055f) * (1.0f / 1.055f), 2.4f);
}
__device__ __forceinline__ void get_lohi(int img, float* lo, float* hi) {
#pragma unroll
    for (int c = 0; c < 3; c++) {
        float l = fdec(g_mm[img * 3 + c]) - 0.01f;
        float h = fdec(g_mm[6 + img * 3 + c]) + 0.01f;
        if (h - l < 1e-4f) { l -= 0.05f; h += 0.05f; }
        lo[c] = l; hi[c] = h;
    }
}

// ---------------- init: u=1, emd=0, minmax sentinels ----------------
__global__ void init_kernel() {
    int idx = blockIdx.x * blockDim.x + threadIdx.x;   // grid = PCOUNT blocks x NB threads
    g_u[idx] = 1.0f;
    if (idx < PCOUNT) g_emd[idx] = 0.0f;
    if (idx < 6) g_mm[idx] = 0xFFFFFFFFu;
    else if (idx < 12) g_mm[idx] = 0u;
}

// ---------------- sRGB -> OKLab + per-channel global min/max ----------------
__global__ void oklab_kernel(const float* __restrict__ ref, const float* __restrict__ tgt) {
    const int img = blockIdx.y;
    const float* __restrict__ in = img ? tgt : ref;
    float* __restrict__ outp = g_oklab[img];
    float mn0 = 1e30f, mn1 = 1e30f, mn2 = 1e30f;
    float mx0 = -1e30f, mx1 = -1e30f, mx2 = -1e30f;

    for (int idx = blockIdx.x * blockDim.x + threadIdx.x; idx < 4 * NPIX;
         idx += gridDim.x * blockDim.x) {
        int b = idx >> 16;
        int hw = idx & 65535;
        int base = b * 3 * NPIX + hw;
        float r  = srgb_lin(in[base]);
        float g  = srgb_lin(in[base + NPIX]);
        float bl = srgb_lin(in[base + 2 * NPIX]);
        float l = 0.4122214708f * r + 0.5363325363f * g + 0.0514459929f * bl;
        float m = 0.2119034982f * r + 0.6806995451f * g + 0.1073969566f * bl;
        float s = 0.0883024619f * r + 0.2817188376f * g + 0.6299787005f * bl;
        l = fmaxf(l, 0.0f); m = fmaxf(m, 0.0f); s = fmaxf(s, 0.0f);
        float lg = (l > 0.0f) ? cbrtf(fmaxf(l, 1e-12f)) : 0.0f;
        float mg = (m > 0.0f) ? cbrtf(fmaxf(m, 1e-12f)) : 0.0f;
        float sg = (s > 0.0f) ? cbrtf(fmaxf(s, 1e-12f)) : 0.0f;
        float L = 0.2104542553f * lg + 0.793617785f  * mg - 0.0040720468f * sg;
        float A = 1.9779984951f * lg - 2.428592205f  * mg + 0.4505937099f * sg;
        float B = 0.0259040371f * lg + 0.7827717662f * mg - 0.808675766f  * sg;
        outp[base] = L; outp[base + NPIX] = A; outp[base + 2 * NPIX] = B;
        mn0 = fminf(mn0, L); mx0 = fmaxf(mx0, L);
        mn1 = fminf(mn1, A); mx1 = fmaxf(mx1, A);
        mn2 = fminf(mn2, B); mx2 = fmaxf(mx2, B);
    }
#pragma unroll
    for (int o = 16; o > 0; o >>= 1) {
        mn0 = fminf(mn0, __shfl_down_sync(0xffffffffu, mn0, o));
        mn1 = fminf(mn1, __shfl_down_sync(0xffffffffu, mn1, o));
        mn2 = fminf(mn2, __shfl_down_sync(0xffffffffu, mn2, o));
        mx0 = fmaxf(mx0, __shfl_down_sync(0xffffffffu, mx0, o));
        mx1 = fmaxf(mx1, __shfl_down_sync(0xffffffffu, mx1, o));
        mx2 = fmaxf(mx2, __shfl_down_sync(0xffffffffu, mx2, o));
    }
    if ((threadIdx.x & 31) == 0) {
        atomicMin(&g_mm[img * 3 + 0], fenc(mn0));
        atomicMin(&g_mm[img * 3 + 1], fenc(mn1));
        atomicMin(&g_mm[img * 3 + 2], fenc(mn2));
        atomicMax(&g_mm[6 + img * 3 + 0], fenc(mx0));
        atomicMax(&g_mm[6 + img * 3 + 1], fenc(mx1));
        atomicMax(&g_mm[6 + img * 3 + 2], fenc(mx2));
    }
}

// ---------------- build K = exp(-cost/REG) and KC = K*cost on averaged grid ----------------
__global__ void buildK_kernel() {
    int i = blockIdx.x, j = threadIdx.x;
    float lor[3], hir[3], lot[3], hit[3];
    get_lohi(0, lor, hir);
    get_lohi(1, lot, hit);
    float step[3];
#pragma unroll
    for (int c = 0; c < 3; c++)
        step[c] = ((hir[c] - lor[c]) + (hit[c] - lot[c])) * 0.5f * 0.125f;
    int i0 = i >> 6, i1 = (i >> 3) & 7, i2 = i & 7;
    int j0 = j >> 6, j1 = (j >> 3) & 7, j2 = j & 7;
    float d0 = step[0] * (float)(i0 - j0);
    float d1 = step[1] * (float)(i1 - j1);
    float d2 = step[2] * (float)(i2 - j2);
    float dd = d0 * d0 + d1 * d1 + d2 * d2;
    float cost = (dd > 0.0f) ? sqrtf(dd) : 0.0f;
    float Kv = expf(-cost * 10.0f);        // REG = 0.1
    g_K[i * NB + j]  = Kv;
    g_KC[i * NB + j] = Kv * cost;
}

// ---------------- per-patch histograms (separable nearest-center binning) ----------------
__global__ void hist_kernel() {
    const int img = blockIdx.y, p = blockIdx.x, t = threadIdx.x;
    __shared__ float h[NB];
    __shared__ float lo_s[3], inv_s[3];
    if (t == 0) {
        float lo[3], hi[3];
        get_lohi(img, lo, hi);
#pragma unroll
        for (int c = 0; c < 3; c++) { lo_s[c] = lo[c]; inv_s[c] = 8.0f / (hi[c] - lo[c]); }
    }
    h[t] = 0.0f; h[t + 256] = 0.0f;
    __syncthreads();

    int b = p >> 8, ph = (p >> 4) & 15, pw = p & 15;
    int py = t >> 4, px = t & 15;
    int hh = (ph << 4) + py, ww = (pw << 4) + px;
    int base = b * 3 * NPIX + hh * 256 + ww;
    const float* ok = g_oklab[img];
    float xL = ok[base], xA = ok[base + NPIX], xB = ok[base + 2 * NPIX];
    int i0 = (int)floorf((xL - lo_s[0]) * inv_s[0]); i0 = min(7, max(0, i0));
    int i1 = (int)floorf((xA - lo_s[1]) * inv_s[1]); i1 = min(7, max(0, i1));
    int i2 = (int)floorf((xB - lo_s[2]) * inv_s[2]); i2 = min(7, max(0, i2));
    atomicAdd(&h[(i0 << 6) | (i1 << 3) | i2], 1.0f);
    __syncthreads();

    float* dst = &g_hist[img][p * NB];
    dst[t]       = h[t]       * (1.0f / 256.0f);
    dst[t + 256] = h[t + 256] * (1.0f / 256.0f);
}

// ---------------- sinkhorn GEMM: split-K (2 warp groups), f32x2 FMA, dup-B ----------------
// mode 0: v = ht / (u@K + eps);  mode 1: u = hr / (v@K + eps);  mode 2: emd += u . (v@KC)
__global__ void __launch_bounds__(256) sink_kernel(int mode) {
    extern __shared__ float sm[];
    float* AsAll = sm;              // [2][2][16][64]
    float* BsAll = sm + 4096;       // [2][2][16][128]  (values duplicated as pairs)
    float* stage = sm;              // epilogue reuse: [32][128]
    float* red   = sm + 4096;       // mode-2 reuse: [64][16]

    const float* Ap; const float* numer; float* outp; const float* Km;
    if (mode == 0)      { Ap = g_u; numer = g_hist[1]; outp = g_v; Km = g_K;  }
    else if (mode == 1) { Ap = g_v; numer = g_hist[0]; outp = g_u; Km = g_K;  }
    else                { Ap = g_v; numer = nullptr;   outp = nullptr; Km = g_KC; }

    const int tid = threadIdx.x;
    const int g = tid >> 7, gt = tid & 127;
    const int tx = gt & 15;             // col group: cols tx*4 .. tx*4+3
    const int ty = gt >> 4;             // row group: rows ty*8 .. ty*8+7 (4 pairs)
    const int row0 = blockIdx.y * BM, col0 = blockIdx.x * BN;

    // A loader: row ra, k offset ka (8 floats)
    const int ra = gt >> 1, ka = (gt & 1) * 8;
    // B loader: k row kb, n offset nbo (8 floats -> 16 duplicated)
    const int kb = gt >> 3, nbo = (gt & 7) * 8;

    float* Asg = AsAll + g * 2048;      // 2 bufs x 16 x 64
    float* Bsg = BsAll + g * 4096;      // 2 bufs x 16 x 128
    const float* Ag = Ap + (size_t)(row0 + ra) * NB + g * KHALF + ka;
    const float* Bg = Km + (size_t)(g * KHALF + kb) * NB + col0 + nbo;

    ull acc[4][4];
#pragma unroll
    for (int i = 0; i < 4; i++)
#pragma unroll
        for (int j = 0; j < 4; j++) acc[i][j] = 0ull;

    // prologue: load chunk 0 of this group's K range
    float4 a0 = *(const float4*)(Ag);
    float4 a1 = *(const float4*)(Ag + 4);
    float4 b0 = *(const float4*)(Bg);
    float4 b1 = *(const float4*)(Bg + 4);
    {
        float av[8] = {a0.x, a0.y, a0.z, a0.w, a1.x, a1.y, a1.z, a1.w};
#pragma unroll
        for (int j = 0; j < 8; j++) Asg[(ka + j) * 64 + ra] = av[j];
        float* d = Bsg + kb * 128 + nbo * 2;
        *(float4*)(d)      = make_float4(b0.x, b0.x, b0.y, b0.y);
        *(float4*)(d + 4)  = make_float4(b0.z, b0.z, b0.w, b0.w);
        *(float4*)(d + 8)  = make_float4(b1.x, b1.x, b1.y, b1.y);
        *(float4*)(d + 12) = make_float4(b1.z, b1.z, b1.w, b1.w);
    }
    GBAR(g);

    int buf = 0;
    for (int k0 = 0; k0 < NKC; k0++) {
        if (k0 + 1 < NKC) {
            const float* Agn = Ag + (k0 + 1) * BK;
            const float* Bgn = Bg + (size_t)(k0 + 1) * BK * NB;
            a0 = *(const float4*)(Agn);
            a1 = *(const float4*)(Agn + 4);
            b0 = *(const float4*)(Bgn);
            b1 = *(const float4*)(Bgn + 4);
        }
        const float* Asb = Asg + buf * 1024;
        const float* Bsb = Bsg + buf * 2048;
#pragma unroll
        for (int kk = 0; kk < BK; kk++) {
            const ull* ap = (const ull*)(Asb + kk * 64 + ty * 8);
            const ull* bp = (const ull*)(Bsb + kk * 128 + tx * 8);
            ull a0p = ap[0], a1p = ap[1], a2p = ap[2], a3p = ap[3];
            ull bb0 = bp[0], bb1 = bp[1], bb2 = bp[2], bb3 = bp[3];
            ffma2(acc[0][0], a0p, bb0); ffma2(acc[0][1], a0p, bb1);
            ffma2(acc[0][2], a0p, bb2); ffma2(acc[0][3], a0p, bb3);
            ffma2(acc[1][0], a1p, bb0); ffma2(acc[1][1], a1p, bb1);
            ffma2(acc[1][2], a1p, bb2); ffma2(acc[1][3], a1p, bb3);
            ffma2(acc[2][0], a2p, bb0); ffma2(acc[2][1], a2p, bb1);
            ffma2(acc[2][2], a2p, bb2); ffma2(acc[2][3], a2p, bb3);
            ffma2(acc[3][0], a3p, bb0); ffma2(acc[3][1], a3p, bb1);
            ffma2(acc[3][2], a3p, bb2); ffma2(acc[3][3], a3p, bb3);
        }
        if (k0 + 1 < NKC) {
            float* Asn = Asg + (buf ^ 1) * 1024;
            float* Bsn = Bsg + (buf ^ 1) * 2048;
            float av[8] = {a0.x, a0.y, a0.z, a0.w, a1.x, a1.y, a1.z, a1.w};
#pragma unroll
            for (int j = 0; j < 8; j++) Asn[(ka + j) * 64 + ra] = av[j];
            float* d = Bsn + kb * 128 + nbo * 2;
            *(float4*)(d)      = make_float4(b0.x, b0.x, b0.y, b0.y);
            *(float4*)(d + 4)  = make_float4(b0.z, b0.z, b0.w, b0.w);
            *(float4*)(d + 8)  = make_float4(b1.x, b1.x, b1.y, b1.y);
            *(float4*)(d + 12) = make_float4(b1.z, b1.z, b1.w, b1.w);
            GBAR(g);
            buf ^= 1;
        }
    }

    // unpack accumulators to fp32
    float accf[32];
#pragma unroll
    for (int pr = 0; pr < 4; pr++)
#pragma unroll
        for (int c = 0; c < 4; c++) {
            accf[(pr * 4 + c) * 2]     = lo_f(acc[pr][c]);
            accf[(pr * 4 + c) * 2 + 1] = hi_f(acc[pr][c]);
        }

    // cross-group reduction: group 1 stages, group 0 combines + epilogue
    __syncthreads();
    if (g == 1) {
#pragma unroll
        for (int i = 0; i < 32; i++) stage[i * 128 + gt] = accf[i];
    }
    __syncthreads();
    if (g == 0) {
#pragma unroll
        for (int i = 0; i < 32; i++) accf[i] += stage[i * 128 + gt];

        if (mode != 2) {
#pragma unroll
            for (int pr = 0; pr < 4; pr++) {
                int rlo = row0 + ty * 8 + pr * 2;
                int c = col0 + tx * 4;
                float4 nlo = *(const float4*)(numer + (size_t)rlo * NB + c);
                float4 nhi = *(const float4*)(numer + (size_t)(rlo + 1) * NB + c);
                float4 olo, ohi;
                olo.x = nlo.x / (accf[(pr * 4 + 0) * 2] + SINK_EPS);
                olo.y = nlo.y / (accf[(pr * 4 + 1) * 2] + SINK_EPS);
                olo.z = nlo.z / (accf[(pr * 4 + 2) * 2] + SINK_EPS);
                olo.w = nlo.w / (accf[(pr * 4 + 3) * 2] + SINK_EPS);
                ohi.x = nhi.x / (accf[(pr * 4 + 0) * 2 + 1] + SINK_EPS);
                ohi.y = nhi.y / (accf[(pr * 4 + 1) * 2 + 1] + SINK_EPS);
                ohi.z = nhi.z / (accf[(pr * 4 + 2) * 2 + 1] + SINK_EPS);
                ohi.w = nhi.w / (accf[(pr * 4 + 3) * 2 + 1] + SINK_EPS);
                *(float4*)(outp + (size_t)rlo * NB + c) = olo;
                *(float4*)(outp + (size_t)(rlo + 1) * NB + c) = ohi;
            }
        } else {
#pragma unroll
            for (int pr = 0; pr < 4; pr++) {
                int rlo = row0 + ty * 8 + pr * 2;
                int c = col0 + tx * 4;
                float4 ulo = *(const float4*)(g_u + (size_t)rlo * NB + c);
                float4 uhi = *(const float4*)(g_u + (size_t)(rlo + 1) * NB + c);
                float slo = accf[(pr * 4 + 0) * 2] * ulo.x + accf[(pr * 4 + 1) * 2] * ulo.y
                          + accf[(pr * 4 + 2) * 2] * ulo.z + accf[(pr * 4 + 3) * 2] * ulo.w;
                float shi = accf[(pr * 4 + 0) * 2 + 1] * uhi.x + accf[(pr * 4 + 1) * 2 + 1] * uhi.y
                          + accf[(pr * 4 + 2) * 2 + 1] * uhi.z + accf[(pr * 4 + 3) * 2 + 1] * uhi.w;
                red[(ty * 8 + pr * 2) * 16 + tx]     = slo;
                red[(ty * 8 + pr * 2 + 1) * 16 + tx] = shi;
            }
        }
    }
    if (mode == 2) {
        __syncthreads();
        if (tid < BM) {
            float tot = 0.0f;
#pragma unroll
            for (int q = 0; q < 16; q++) tot += red[tid * 16 + q];
            atomicAdd(&g_emd[row0 + tid], tot);
        }
    }
}

// ---------------- half-pixel bilinear upsample 16x16 -> 256x256 ----------------
__global__ void upsample_kernel(float* __restrict__ out) {
    int idx = blockIdx.x * blockDim.x + threadIdx.x;
    if (idx >= 4 * NPIX) return;
    int b = idx >> 16, y = (idx >> 8) & 255, x = idx & 255;
    float fy = (y + 0.5f) * 0.0625f - 0.5f;
    float fx = (x + 0.5f) * 0.0625f - 0.5f;
    int y0 = (int)floorf(fy); float wy = fy - (float)y0;
    int x0 = (int)floorf(fx); float wx = fx - (float)x0;
    int y0c = min(15, max(0, y0)), y1c = min(15, max(0, y0 + 1));
    int x0c = min(15, max(0, x0)), x1c = min(15, max(0, x0 + 1));
    const float* e = g_emd + b * 256;
    float v00 = e[y0c * 16 + x0c], v01 = e[y0c * 16 + x1c];
    float v10 = e[y1c * 16 + x0c], v11 = e[y1c * 16 + x1c];
    v00 = isfinite(v00) ? v00 : 0.0f;
    v01 = isfinite(v01) ? v01 : 0.0f;
    v10 = isfinite(v10) ? v10 : 0.0f;
    v11 = isfinite(v11) ? v11 : 0.0f;
    float t0 = v00 + (v01 - v00) * wx;
    float t1 = v10 + (v11 - v10) * wx;
    out[idx] = t0 + (t1 - t0) * wy;
}

// ---------------- launcher ----------------
extern "C" void kernel_launch(void* const* d_in, const int* in_sizes, int n_in,
                              void* d_out, int out_size) {
    (void)in_sizes; (void)n_in; (void)out_size;
    const float* ref = (const float*)d_in[0];
    const float* tgt = (const float*)d_in[1];
    float* out = (float*)d_out;

    static int smem_set = 0;
    if (!smem_set) {
        cudaFuncSetAttribute(sink_kernel, cudaFuncAttributeMaxDynamicSharedMemorySize,
                             SMEM_FLOATS * 4);
        smem_set = 1;
    }

    init_kernel<<<PCOUNT, NB>>>();
    oklab_kernel<<<dim3(256, 2), 256>>>(ref, tgt);
    buildK_kernel<<<NB, NB>>>();
    hist_kernel<<<dim3(PCOUNT, 2), 256>>>();

    dim3 gg(NB / BN, PCOUNT / BM);                      // (8, 16) = 128 CTAs
    for (int it = 0; it < 20; it++) {
        sink_kernel<<<gg, 256, SMEM_FLOATS * 4>>>(0);   // v-update
        sink_kernel<<<gg, 256, SMEM_FLOATS * 4>>>(1);   // u-update
    }
    sink_kernel<<<gg, 256, SMEM_FLOATS * 4>>>(2);       // emd accumulation

    upsample_kernel<<<(4 * NPIX + 255) / 256, 256>>>(out);
}

// round 7
// speedup vs baseline: 1.7329x; 1.7329x over previous
#include <cuda_runtime.h>
#include <math.h>
#include <stdint.h>

#define NPIX   65536      // 256*256
#define PCOUNT 1024       // 4 * 16 * 16 patches
#define NB     512        // 8^3 bins
#define SINK_EPS 1e-6f

#define BK 16
#define KHALF 256                 // K range per CTA (split-K x2)
#define NKC (KHALF / BK)          // 16 chunks

// ---------------- scratch (static device globals; no allocation) ----------------
__device__ float    g_oklab[2][4 * 3 * NPIX];   // [img][b][c][h][w]
__device__ unsigned g_mm[12];                   // [0:6) min enc (img,c), [6:12) max enc
__device__ float    g_hist[2][PCOUNT * NB];     // normalized (counts/256)
__device__ float    g_Du[2][PCOUNT * NB];       // split-K partials of (v@K)
__device__ float    g_Dv[2][PCOUNT * NB];       // split-K partials of (u@K)
__device__ float    g_K[NB * NB];
__device__ float    g_KC[NB * NB];              // K * cost
__device__ float    g_emd[PCOUNT];

typedef unsigned long long ull;

// packed fp32x2 FMA: d = a*b + d (two independent lanes)
__device__ __forceinline__ void ffma2(ull& d, ull a, ull b) {
    asm("fma.rn.f32x2 %0, %1, %2, %0;" : "+l"(d) : "l"(a), "l"(b));
}
__device__ __forceinline__ ull dup_f32(float x) {
    ull r;
    unsigned u = __float_as_uint(x);
    asm("mov.b64 %0, {%1, %1};" : "=l"(r) : "r"(u));
    return r;
}
__device__ __forceinline__ float lo_f(ull p) { return __uint_as_float((unsigned)p); }
__device__ __forceinline__ float hi_f(ull p) { return __uint_as_float((unsigned)(p >> 32)); }

// ---------------- helpers ----------------
__device__ __forceinline__ unsigned fenc(float f) {
    unsigned u = __float_as_uint(f);
    return (u & 0x80000000u) ? ~u : (u | 0x80000000u);
}
__device__ __forceinline__ float fdec(unsigned u) {
    return __uint_as_float((u & 0x80000000u) ? (u ^ 0x80000000u) : ~u);
}
__device__ __forceinline__ float srgb_lin(float x) {
    x = fminf(fmaxf(x, 0.0f), 1.0f);
    return (x <= 0.04045f) ? x * (1.0f / 12.92f)
                           : powf((x + 0.055f) * (1.0f / 1.055f), 2.4f);
}
__device__ __forceinline__ void get_lohi(int img, float* lo, float* hi) {
#pragma unroll
    for (int c = 0; c < 3; c++) {
        float l = fdec(g_mm[img * 3 + c]) - 0.01f;
        float h = fdec(g_mm[6 + img * 3 + c]) + 0.01f;
        if (h - l < 1e-4f) { l -= 0.05f; h += 0.05f; }
        lo[c] = l; hi[c] = h;
    }
}

// ---------------- init: emd=0, minmax sentinels ----------------
__global__ void init_kernel() {
    int idx = threadIdx.x;                       // one block of 1024
    g_emd[idx] = 0.0f;
    if (idx < 6) g_mm[idx] = 0xFFFFFFFFu;
    else if (idx < 12) g_mm[idx] = 0u;
}

// ---------------- sRGB -> OKLab + per-channel global min/max ----------------
__global__ void oklab_kernel(const float* __restrict__ ref, const float* __restrict__ tgt) {
    const int img = blockIdx.y;
    const float* __restrict__ in = img ? tgt : ref;
    float* __restrict__ outp = g_oklab[img];
    float mn0 = 1e30f, mn1 = 1e30f, mn2 = 1e30f;
    float mx0 = -1e30f, mx1 = -1e30f, mx2 = -1e30f;

    for (int idx = blockIdx.x * blockDim.x + threadIdx.x; idx < 4 * NPIX;
         idx += gridDim.x * blockDim.x) {
        int b = idx >> 16;
        int hw = idx & 65535;
        int base = b * 3 * NPIX + hw;
        float r  = srgb_lin(in[base]);
        float g  = srgb_lin(in[base + NPIX]);
        float bl = srgb_lin(in[base + 2 * NPIX]);
        float l = 0.4122214708f * r + 0.5363325363f * g + 0.0514459929f * bl;
        float m = 0.2119034982f * r + 0.6806995451f * g + 0.1073969566f * bl;
        float s = 0.0883024619f * r + 0.2817188376f * g + 0.6299787005f * bl;
        l = fmaxf(l, 0.0f); m = fmaxf(m, 0.0f); s = fmaxf(s, 0.0f);
        float lg = (l > 0.0f) ? cbrtf(fmaxf(l, 1e-12f)) : 0.0f;
        float mg = (m > 0.0f) ? cbrtf(fmaxf(m, 1e-12f)) : 0.0f;
        float sg = (s > 0.0f) ? cbrtf(fmaxf(s, 1e-12f)) : 0.0f;
        float L = 0.2104542553f * lg + 0.793617785f  * mg - 0.0040720468f * sg;
        float A = 1.9779984951f * lg - 2.428592205f  * mg + 0.4505937099f * sg;
        float B = 0.0259040371f * lg + 0.7827717662f * mg - 0.808675766f  * sg;
        outp[base] = L; outp[base + NPIX] = A; outp[base + 2 * NPIX] = B;
        mn0 = fminf(mn0, L); mx0 = fmaxf(mx0, L);
        mn1 = fminf(mn1, A); mx1 = fmaxf(mx1, A);
        mn2 = fminf(mn2, B); mx2 = fmaxf(mx2, B);
    }
#pragma unroll
    for (int o = 16; o > 0; o >>= 1) {
        mn0 = fminf(mn0, __shfl_down_sync(0xffffffffu, mn0, o));
        mn1 = fminf(mn1, __shfl_down_sync(0xffffffffu, mn1, o));
        mn2 = fminf(mn2, __shfl_down_sync(0xffffffffu, mn2, o));
        mx0 = fmaxf(mx0, __shfl_down_sync(0xffffffffu, mx0, o));
        mx1 = fmaxf(mx1, __shfl_down_sync(0xffffffffu, mx1, o));
        mx2 = fmaxf(mx2, __shfl_down_sync(0xffffffffu, mx2, o));
    }
    if ((threadIdx.x & 31) == 0) {
        atomicMin(&g_mm[img * 3 + 0], fenc(mn0));
        atomicMin(&g_mm[img * 3 + 1], fenc(mn1));
        atomicMin(&g_mm[img * 3 + 2], fenc(mn2));
        atomicMax(&g_mm[6 + img * 3 + 0], fenc(mx0));
        atomicMax(&g_mm[6 + img * 3 + 1], fenc(mx1));
        atomicMax(&g_mm[6 + img * 3 + 2], fenc(mx2));
    }
}

// ---------------- build K = exp(-cost/REG) and KC = K*cost on averaged grid ----------------
__global__ void buildK_kernel() {
    int i = blockIdx.x, j = threadIdx.x;
    float lor[3], hir[3], lot[3], hit[3];
    get_lohi(0, lor, hir);
    get_lohi(1, lot, hit);
    float step[3];
#pragma unroll
    for (int c = 0; c < 3; c++)
        step[c] = ((hir[c] - lor[c]) + (hit[c] - lot[c])) * 0.5f * 0.125f;
    int i0 = i >> 6, i1 = (i >> 3) & 7, i2 = i & 7;
    int j0 = j >> 6, j1 = (j >> 3) & 7, j2 = j & 7;
    float d0 = step[0] * (float)(i0 - j0);
    float d1 = step[1] * (float)(i1 - j1);
    float d2 = step[2] * (float)(i2 - j2);
    float dd = d0 * d0 + d1 * d1 + d2 * d2;
    float cost = (dd > 0.0f) ? sqrtf(dd) : 0.0f;
    float Kv = expf(-cost * 10.0f);        // REG = 0.1
    g_K[i * NB + j]  = Kv;
    g_KC[i * NB + j] = Kv * cost;
}

// ---------------- per-patch histograms (separable nearest-center binning) ----------------
__global__ void hist_kernel() {
    const int img = blockIdx.y, p = blockIdx.x, t = threadIdx.x;
    __shared__ float h[NB];
    __shared__ float lo_s[3], inv_s[3];
    if (t == 0) {
        float lo[3], hi[3];
        get_lohi(img, lo, hi);
#pragma unroll
        for (int c = 0; c < 3; c++) { lo_s[c] = lo[c]; inv_s[c] = 8.0f / (hi[c] - lo[c]); }
    }
    h[t] = 0.0f; h[t + 256] = 0.0f;
    __syncthreads();

    int b = p >> 8, ph = (p >> 4) & 15, pw = p & 15;
    int py = t >> 4, px = t & 15;
    int hh = (ph << 4) + py, ww = (pw << 4) + px;
    int base = b * 3 * NPIX + hh * 256 + ww;
    const float* ok = g_oklab[img];
    float xL = ok[base], xA = ok[base + NPIX], xB = ok[base + 2 * NPIX];
    int i0 = (int)floorf((xL - lo_s[0]) * inv_s[0]); i0 = min(7, max(0, i0));
    int i1 = (int)floorf((xA - lo_s[1]) * inv_s[1]); i1 = min(7, max(0, i1));
    int i2 = (int)floorf((xB - lo_s[2]) * inv_s[2]); i2 = min(7, max(0, i2));
    atomicAdd(&h[(i0 << 6) | (i1 << 3) | i2], 1.0f);
    __syncthreads();

    float* dst = &g_hist[img][p * NB];
    dst[t]       = h[t]       * (1.0f / 256.0f);
    dst[t + 256] = h[t + 256] * (1.0f / 256.0f);
}

// ---------------- sinkhorn GEMM: split-K across CTAs, lazy operand reconstruction ----
// A-operand is reconstructed on load as numerA/(Da0+Da1+eps) (or ones for mode 0).
// Output = raw partial (A @ Km) for this CTA's K-half.
// mode 0: first v-update: A=1,        out g_Dv[kh], Km=K
// mode 1: v-update:       A=u(recon), out g_Dv[kh], Km=K   (numer=hr, D=g_Du)
// mode 2: u-update:       A=v(recon), out g_Du[kh], Km=K   (numer=ht, D=g_Dv)
// mode 3: emd:            A=v(recon), Km=KC; epilogue dots with u(recon), atomicAdd g_emd
__global__ void __launch_bounds__(256) sink_kernel(int mode) {
    __shared__ float As[2][BK][64];      // 8KB
    __shared__ float Bs[2][BK][128];     // 16KB

    const int tid = threadIdx.x;
    const int tx = tid & 31;             // lane -> cols tx*4 .. tx*4+3
    const int ty = tid >> 5;             // warp -> rows ty*8 .. ty*8+7 (4 pairs)
    const int col0 = blockIdx.x * 128;
    const int row0 = blockIdx.y * 64;
    const int kh = blockIdx.z;
    const int koff = kh * KHALF;

    const float *numerA = nullptr, *Da0 = nullptr, *Da1 = nullptr;
    const float* Km = g_K;
    float* outD = nullptr;
    const bool ones = (mode == 0);
    if (mode == 0)      { outD = g_Dv[kh]; }
    else if (mode == 1) { numerA = g_hist[0]; Da0 = g_Du[0]; Da1 = g_Du[1]; outD = g_Dv[kh]; }
    else if (mode == 2) { numerA = g_hist[1]; Da0 = g_Dv[0]; Da1 = g_Dv[1]; outD = g_Du[kh]; }
    else                { numerA = g_hist[1]; Da0 = g_Dv[0]; Da1 = g_Dv[1]; Km = g_KC; }

    // loaders
    const int ra = tid >> 2, ka = (tid & 3) * 4;        // A: 64 rows x 16k / 4 = 256
    const int kb = tid >> 4, nbo = (tid & 15) * 8;      // B: 16k x 128n / 8 = 256
    const size_t aoff = (size_t)(row0 + ra) * NB + koff + ka;
    const size_t boff = (size_t)(koff + kb) * NB + col0 + nbo;

    if (ones) {     // A tile is all-ones for the whole kernel; fill both buffers once
        float* af = (float*)As;
        for (int i = tid; i < 2 * BK * 64; i += 256) af[i] = 1.0f;
    }

    ull acc[4][4];
#pragma unroll
    for (int i = 0; i < 4; i++)
#pragma unroll
        for (int j = 0; j < 4; j++) acc[i][j] = 0ull;

    // prologue: load chunk 0
    float4 an, ad0, ad1, b0, b1;
    if (!ones) {
        an  = *(const float4*)(numerA + aoff);
        ad0 = *(const float4*)(Da0 + aoff);
        ad1 = *(const float4*)(Da1 + aoff);
    }
    b0 = *(const float4*)(Km + boff);
    b1 = *(const float4*)(Km + boff + 4);
    if (!ones) {
        As[0][ka + 0][ra] = __fdividef(an.x, ad0.x + ad1.x + SINK_EPS);
        As[0][ka + 1][ra] = __fdividef(an.y, ad0.y + ad1.y + SINK_EPS);
        As[0][ka + 2][ra] = __fdividef(an.z, ad0.z + ad1.z + SINK_EPS);
        As[0][ka + 3][ra] = __fdividef(an.w, ad0.w + ad1.w + SINK_EPS);
    }
    *(float4*)(&Bs[0][kb][nbo])     = b0;
    *(float4*)(&Bs[0][kb][nbo + 4]) = b1;
    __syncthreads();

    int buf = 0;
    for (int kc = 0; kc < NKC; kc++) {
        if (kc + 1 < NKC) {
            if (!ones) {
                an  = *(const float4*)(numerA + aoff + (kc + 1) * BK);
                ad0 = *(const float4*)(Da0 + aoff + (kc + 1) * BK);
                ad1 = *(const float4*)(Da1 + aoff + (kc + 1) * BK);
            }
            b0 = *(const float4*)(Km + boff + (size_t)(kc + 1) * BK * NB);
            b1 = *(const float4*)(Km + boff + (size_t)(kc + 1) * BK * NB + 4);
        }
#pragma unroll
        for (int kk = 0; kk < BK; kk++) {
            const ull* ap = (const ull*)(&As[buf][kk][ty * 8]);   // warp-uniform -> broadcast
            ull a0p = ap[0], a1p = ap[1], a2p = ap[2], a3p = ap[3];
            float4 bq = *(const float4*)(&Bs[buf][kk][tx * 4]);
            ull bb0 = dup_f32(bq.x), bb1 = dup_f32(bq.y);
            ull bb2 = dup_f32(bq.z), bb3 = dup_f32(bq.w);
            ffma2(acc[0][0], a0p, bb0); ffma2(acc[0][1], a0p, bb1);
            ffma2(acc[0][2], a0p, bb2); ffma2(acc[0][3], a0p, bb3);
            ffma2(acc[1][0], a1p, bb0); ffma2(acc[1][1], a1p, bb1);
            ffma2(acc[1][2], a1p, bb2); ffma2(acc[1][3], a1p, bb3);
            ffma2(acc[2][0], a2p, bb0); ffma2(acc[2][1], a2p, bb1);
            ffma2(acc[2][2], a2p, bb2); ffma2(acc[2][3], a2p, bb3);
            ffma2(acc[3][0], a3p, bb0); ffma2(acc[3][1], a3p, bb1);
            ffma2(acc[3][2], a3p, bb2); ffma2(acc[3][3], a3p, bb3);
        }
        if (kc + 1 < NKC) {
            int nbuf = buf ^ 1;
            if (!ones) {
                As[nbuf][ka + 0][ra] = __fdividef(an.x, ad0.x + ad1.x + SINK_EPS);
                As[nbuf][ka + 1][ra] = __fdividef(an.y, ad0.y + ad1.y + SINK_EPS);
                As[nbuf][ka + 2][ra] = __fdividef(an.z, ad0.z + ad1.z + SINK_EPS);
                As[nbuf][ka + 3][ra] = __fdividef(an.w, ad0.w + ad1.w + SINK_EPS);
            }
            *(float4*)(&Bs[nbuf][kb][nbo])     = b0;
            *(float4*)(&Bs[nbuf][kb][nbo + 4]) = b1;
            __syncthreads();
            buf = nbuf;
        }
    }

    if (mode != 3) {
        // store raw partials (coalesced float4 per row)
#pragma unroll
        for (int pr = 0; pr < 4; pr++) {
            int rlo = row0 + ty * 8 + pr * 2;
            size_t gi = (size_t)rlo * NB + col0 + tx * 4;
            float4 olo = make_float4(lo_f(acc[pr][0]), lo_f(acc[pr][1]),
                                     lo_f(acc[pr][2]), lo_f(acc[pr][3]));
            float4 ohi = make_float4(hi_f(acc[pr][0]), hi_f(acc[pr][1]),
                                     hi_f(acc[pr][2]), hi_f(acc[pr][3]));
            *(float4*)(outD + gi)      = olo;
            *(float4*)(outD + gi + NB) = ohi;
        }
    } else {
        // emd partial: sum over this CTA's N-range of u(r,c) * P(r,c)
        const float* hr  = g_hist[0];
        const float* du0 = g_Du[0];
        const float* du1 = g_Du[1];
#pragma unroll
        for (int pr = 0; pr < 4; pr++) {
#pragma unroll
            for (int half = 0; half < 2; half++) {
                int r = row0 + ty * 8 + pr * 2 + half;
                size_t gi = (size_t)r * NB + col0 + tx * 4;
                float4 n4 = *(const float4*)(hr + gi);
                float4 d0 = *(const float4*)(du0 + gi);
                float4 d1 = *(const float4*)(du1 + gi);
                float u0 = __fdividef(n4.x, d0.x + d1.x + SINK_EPS);
                float u1 = __fdividef(n4.y, d0.y + d1.y + SINK_EPS);
                float u2 = __fdividef(n4.z, d0.z + d1.z + SINK_EPS);
                float u3 = __fdividef(n4.w, d0.w + d1.w + SINK_EPS);
                float s;
                if (half == 0)
                    s = lo_f(acc[pr][0]) * u0 + lo_f(acc[pr][1]) * u1
                      + lo_f(acc[pr][2]) * u2 + lo_f(acc[pr][3]) * u3;
                else
                    s = hi_f(acc[pr][0]) * u0 + hi_f(acc[pr][1]) * u1
                      + hi_f(acc[pr][2]) * u2 + hi_f(acc[pr][3]) * u3;
#pragma unroll
                for (int o = 16; o > 0; o >>= 1)
                    s += __shfl_xor_sync(0xffffffffu, s, o);
                if (tx == 0) atomicAdd(&g_emd[r], s);
            }
        }
    }
}

// ---------------- half-pixel bilinear upsample 16x16 -> 256x256 ----------------
__global__ void upsample_kernel(float* __restrict__ out) {
    int idx = blockIdx.x * blockDim.x + threadIdx.x;
    if (idx >= 4 * NPIX) return;
    int b = idx >> 16, y = (idx >> 8) & 255, x = idx & 255;
    float fy = (y + 0.5f) * 0.0625f - 0.5f;
    float fx = (x + 0.5f) * 0.0625f - 0.5f;
    int y0 = (int)floorf(fy); float wy = fy - (float)y0;
    int x0 = (int)floorf(fx); float wx = fx - (float)x0;
    int y0c = min(15, max(0, y0)), y1c = min(15, max(0, y0 + 1));
    int x0c = min(15, max(0, x0)), x1c = min(15, max(0, x0 + 1));
    const float* e = g_emd + b * 256;
    float v00 = e[y0c * 16 + x0c], v01 = e[y0c * 16 + x1c];
    float v10 = e[y1c * 16 + x0c], v11 = e[y1c * 16 + x1c];
    v00 = isfinite(v00) ? v00 : 0.0f;
    v01 = isfinite(v01) ? v01 : 0.0f;
    v10 = isfinite(v10) ? v10 : 0.0f;
    v11 = isfinite(v11) ? v11 : 0.0f;
    float t0 = v00 + (v01 - v00) * wx;
    float t1 = v10 + (v11 - v10) * wx;
    out[idx] = t0 + (t1 - t0) * wy;
}

// ---------------- launcher ----------------
extern "C" void kernel_launch(void* const* d_in, const int* in_sizes, int n_in,
                              void* d_out, int out_size) {
    (void)in_sizes; (void)n_in; (void)out_size;
    const float* ref = (const float*)d_in[0];
    const float* tgt = (const float*)d_in[1];
    float* out = (float*)d_out;

    init_kernel<<<1, 1024>>>();
    oklab_kernel<<<dim3(256, 2), 256>>>(ref, tgt);
    buildK_kernel<<<NB, NB>>>();
    hist_kernel<<<dim3(PCOUNT, 2), 256>>>();

    dim3 gg(NB / 128, PCOUNT / 64, 2);                  // (4, 16, 2) = 128 CTAs
    sink_kernel<<<gg, 256>>>(0);                        // v-update, A = ones
    sink_kernel<<<gg, 256>>>(2);                        // u-update
    for (int it = 1; it < 20; it++) {
        sink_kernel<<<gg, 256>>>(1);                    // v-update
        sink_kernel<<<gg, 256>>>(2);                    // u-update
    }
    sink_kernel<<<gg, 256>>>(3);                        // emd accumulation

    upsample_kernel<<<(4 * NPIX + 255) / 256, 256>>>(out);
}